// round 11
// baseline (speedup 1.0000x reference)
#include <cuda_runtime.h>
#include <math.h>

typedef unsigned long long ull;

#define BB 32
#define TT 512
#define EP 512
#define DU 1024
#define OD 10000
#define AD 320
#define LL 128
#define LP1 129
#define NROWS (BB*LP1)      /* 4128 */
#define SOS_EOS (OD-1)

// ---------------- scratch (device globals; no allocation allowed) ----------
__device__ float g_pre[(size_t)BB*TT*AD];       // tanh(hs @ Wenc^T + benc)  [B,T,A]
__device__ float g_zs[(size_t)BB*LP1*DU];       // z1 history               [B,L+1,DU]
__device__ float g_logits[(size_t)NROWS*OD];    // output logits
__device__ float g_z0[BB*DU];
__device__ float g_c0[BB*DU];
__device__ float g_z1[BB*DU];
__device__ float g_c1[BB*DU];
__device__ float g_attc[BB*EP];
__device__ float g_decP[2*BB*AD];               // dec partials (2 k-slices)
__device__ float g_g0P[10*BB*4*DU];             // gates0 partials (10 slices)
__device__ float g_g1P[8*BB*4*DU];              // gates1 partials (8 slices)
__device__ float g_nll[NROWS];
__device__ int   g_corr[NROWS];

// ---------------- packed f32x2 helpers (2x fp32 FMA throughput) ------------
__device__ __forceinline__ ull pk2(float lo, float hi){
    ull r; asm("mov.b64 %0, {%1, %2};" : "=l"(r) : "f"(lo), "f"(hi)); return r;
}
__device__ __forceinline__ void up2(ull v, float &lo, float &hi){
    asm("mov.b64 {%0, %1}, %2;" : "=f"(lo), "=f"(hi) : "l"(v));
}
__device__ __forceinline__ void fma2(ull &acc, ull a, ull b){
    asm("fma.rn.f32x2 %0, %1, %2, %0;" : "+l"(acc) : "l"(a), "l"(b));
}

// ---------------- init ------------------------------------------------------
__global__ void initk(){
    int i = blockIdx.x*256 + threadIdx.x;
    if (i < BB*DU){ g_z0[i]=0.f; g_c0[i]=0.f; g_z1[i]=0.f; g_c1[i]=0.f; }
}

// ---------------- big GEMM: C[M,N] = A[M,K] @ B[N,K]^T + bias, opt tanh ----
// BM=128, BN=64, BK=16, 256 threads, thread tile 8x4, f32x2 accumulation.
__global__ __launch_bounds__(256) void gemm_big(
    const float* __restrict__ A, const float* __restrict__ B,
    const float* __restrict__ bias, float* __restrict__ C,
    int M, int N, int K, int act)
{
    __shared__ float As[16][128];
    __shared__ float Bs[16][64];
    const int t  = threadIdx.x;
    const int m0 = blockIdx.y * 128;
    const int n0 = blockIdx.x * 64;
    const int mt = (t >> 4) * 8;
    const int nt = (t & 15) * 4;

    ull acc[8][2];
#pragma unroll
    for (int i = 0; i < 8; i++){ acc[i][0] = 0ULL; acc[i][1] = 0ULL; }

    for (int k0 = 0; k0 < K; k0 += 16){
#pragma unroll
        for (int l = 0; l < 2; l++){
            int idx = t + 256*l;
            int m = idx >> 2, q = idx & 3;
            float4 v = make_float4(0.f,0.f,0.f,0.f);
            int gm = m0 + m;
            if (gm < M) v = *(const float4*)(A + (size_t)gm*K + k0 + q*4);
            As[q*4+0][m]=v.x; As[q*4+1][m]=v.y; As[q*4+2][m]=v.z; As[q*4+3][m]=v.w;
        }
        {
            int n = t >> 2, q = t & 3;
            float4 v = make_float4(0.f,0.f,0.f,0.f);
            int gn = n0 + n;
            if (gn < N) v = *(const float4*)(B + (size_t)gn*K + k0 + q*4);
            Bs[q*4+0][n]=v.x; Bs[q*4+1][n]=v.y; Bs[q*4+2][n]=v.z; Bs[q*4+3][n]=v.w;
        }
        __syncthreads();
#pragma unroll
        for (int kk = 0; kk < 16; kk++){
            float4 a0 = *(const float4*)&As[kk][mt];
            float4 a1 = *(const float4*)&As[kk][mt+4];
            float4 b  = *(const float4*)&Bs[kk][nt];
            ull b01 = pk2(b.x, b.y), b23 = pk2(b.z, b.w);
            float av[8] = {a0.x,a0.y,a0.z,a0.w,a1.x,a1.y,a1.z,a1.w};
#pragma unroll
            for (int i = 0; i < 8; i++){
                ull a2 = pk2(av[i], av[i]);
                fma2(acc[i][0], a2, b01);
                fma2(acc[i][1], a2, b23);
            }
        }
        __syncthreads();
    }

    float bsv[4];
#pragma unroll
    for (int j = 0; j < 4; j++) bsv[j] = (n0+nt+j < N) ? bias[n0+nt+j] : 0.f;
#pragma unroll
    for (int i = 0; i < 8; i++){
        int gm = m0 + mt + i;
        if (gm >= M) continue;
        float v[4];
        up2(acc[i][0], v[0], v[1]);
        up2(acc[i][1], v[2], v[3]);
#pragma unroll
        for (int j = 0; j < 4; j++){
            int gn = n0 + nt + j;
            if (gn < N){
                float r = v[j] + bsv[j];
                if (act) r = tanhf(r);
                C[(size_t)gm*N + gn] = r;
            }
        }
    }
}

// ---------------- small-M GEMM (M=32) with split-K partial output ----------
// C_partial[s][32][N] = A[32, kslice] @ B[N, kslice]^T ; B split into B1|B2 at K1.
// A is gathered per mode: 0: z0 ; 1: [embed(ys_in[step]) | att_c | z0] ; 2: [z0 | z1]
__global__ __launch_bounds__(256) void gemm_small(
    int mode, int step,
    const float* __restrict__ B1, const float* __restrict__ B2,
    int K1, int K2, int N,
    const float* __restrict__ embed, const int* __restrict__ ys,
    const float* __restrict__ attc,
    const float* __restrict__ x0, const float* __restrict__ x1,
    float* __restrict__ P, int kPerSplit)
{
    __shared__ float As[32*32];    // [k][b]
    __shared__ float Bs[32*128];   // [k][n]
    const int t    = threadIdx.x;
    const int n0   = blockIdx.x * 128;
    const int s    = blockIdx.y;
    const int kbeg = s * kPerSplit;
    const int kend = kbeg + kPerSplit;
    const int nt = (t & 31) * 4;
    const int bt = (t >> 5) * 4;
    const int lb = t >> 3;     // batch row this thread loads (A)
    const int lq = t & 7;      // k-quad

    ull acc[4][2];
#pragma unroll
    for (int i = 0; i < 4; i++){ acc[i][0]=0ULL; acc[i][1]=0ULL; }

    for (int k0 = kbeg; k0 < kend; k0 += 32){
        {   // A tile: 32b x 32k, one float4 per thread, gather by mode
            int kg = k0 + lq*4;
            const float* src;
            if (mode == 1){
                if (kg < DU){
                    int tok = (step == 0) ? SOS_EOS : ys[lb*LL + step - 1];
                    src = embed + (size_t)tok*DU + kg;
                } else if (kg < DU + EP){
                    src = attc + lb*EP + (kg - DU);
                } else {
                    src = x0 + lb*DU + (kg - DU - EP);
                }
            } else if (mode == 2){
                src = (kg < DU) ? (x0 + lb*DU + kg) : (x1 + lb*DU + (kg - DU));
            } else {
                src = x0 + lb*DU + kg;
            }
            float4 v = *(const float4*)src;
            As[(lq*4+0)*32+lb]=v.x; As[(lq*4+1)*32+lb]=v.y;
            As[(lq*4+2)*32+lb]=v.z; As[(lq*4+3)*32+lb]=v.w;
        }
#pragma unroll
        for (int l = 0; l < 4; l++){   // B tile: 128n x 32k
            int idx = t + 256*l;
            int n = idx >> 3, q = idx & 7;
            int gn = n0 + n, kg = k0 + q*4;
            float4 v = make_float4(0.f,0.f,0.f,0.f);
            if (gn < N){
                v = (kg < K1) ? *(const float4*)(B1 + (size_t)gn*K1 + kg)
                              : *(const float4*)(B2 + (size_t)gn*K2 + (kg - K1));
            }
            Bs[(q*4+0)*128+n]=v.x; Bs[(q*4+1)*128+n]=v.y;
            Bs[(q*4+2)*128+n]=v.z; Bs[(q*4+3)*128+n]=v.w;
        }
        __syncthreads();
#pragma unroll
        for (int kk = 0; kk < 32; kk++){
            float4 a = *(const float4*)&As[kk*32 + bt];
            float4 b = *(const float4*)&Bs[kk*128 + nt];
            ull b01 = pk2(b.x,b.y), b23 = pk2(b.z,b.w);
            float av[4] = {a.x,a.y,a.z,a.w};
#pragma unroll
            for (int i = 0; i < 4; i++){
                ull a2 = pk2(av[i], av[i]);
                fma2(acc[i][0], a2, b01);
                fma2(acc[i][1], a2, b23);
            }
        }
        __syncthreads();
    }

#pragma unroll
    for (int i = 0; i < 4; i++){
        int b = bt + i;
        float v[4];
        up2(acc[i][0], v[0], v[1]);
        up2(acc[i][1], v[2], v[3]);
        int gn = n0 + nt;
        if (gn + 3 < N){
            *(float4*)(P + ((size_t)s*BB + b)*N + gn) = make_float4(v[0],v[1],v[2],v[3]);
        } else {
#pragma unroll
            for (int j = 0; j < 4; j++)
                if (gn + j < N) P[((size_t)s*BB + b)*N + gn + j] = v[j];
        }
    }
}

// ---------------- attention: per-batch block (dec partial-sum+tanh, e, softmax, att_c)
__global__ __launch_bounds__(512) void att_kernel(
    const float* __restrict__ hs, const int* __restrict__ hlens)
{
    const int b = blockIdx.x;
    __shared__ float dec_s[AD];
    __shared__ float e_s[TT];
    __shared__ float red[512];
    const int t = threadIdx.x;

    if (t < AD) dec_s[t] = tanhf(g_decP[b*AD + t] + g_decP[(BB + b)*AD + t]);
    __syncthreads();

    // e[t] = sum_a pre[b,t,a]*dec[a]  (warp per t, lanes over a — coalesced)
    const int warp = t >> 5, lane = t & 31;
    for (int tt = warp; tt < TT; tt += 16){
        const float* pr = &g_pre[((size_t)b*TT + tt)*AD];
        float sv = 0.f;
        for (int a = lane; a < AD; a += 32) sv += pr[a]*dec_s[a];
#pragma unroll
        for (int o = 16; o; o >>= 1) sv += __shfl_xor_sync(0xffffffffu, sv, o);
        if (lane == 0) e_s[tt] = sv;
    }
    __syncthreads();

    const int hlen = hlens[b];
    float sv = (t < hlen) ? 2.f*e_s[t] : -1e10f;
    red[t] = sv; __syncthreads();
    for (int o = 256; o; o >>= 1){ if (t < o) red[t] = fmaxf(red[t], red[t+o]); __syncthreads(); }
    float mx = red[0]; __syncthreads();
    float ex = expf(sv - mx);
    red[t] = ex; __syncthreads();
    for (int o = 256; o; o >>= 1){ if (t < o) red[t] += red[t+o]; __syncthreads(); }
    float inv = 1.f / red[0]; __syncthreads();
    e_s[t] = ex * inv;     // reuse e_s as weights
    __syncthreads();

    // att_c[d] = sum_t w[t]*hs[b,t,d]  (thread per d, coalesced over d)
    const float* hb = hs + (size_t)b*TT*EP;
    float a0=0.f, a1=0.f, a2=0.f, a3=0.f;
    const int d = t;
    for (int tt = 0; tt < TT; tt += 4){
        a0 += e_s[tt+0]*hb[(size_t)(tt+0)*EP + d];
        a1 += e_s[tt+1]*hb[(size_t)(tt+1)*EP + d];
        a2 += e_s[tt+2]*hb[(size_t)(tt+2)*EP + d];
        a3 += e_s[tt+3]*hb[(size_t)(tt+3)*EP + d];
    }
    g_attc[b*EP + d] = (a0+a1) + (a2+a3);
}

// ---------------- LSTM cell: reduce split-K partials + biases, gate math ----
__global__ void cellk(const float* __restrict__ P, int S,
                      const float* __restrict__ bi, const float* __restrict__ bh,
                      float* __restrict__ h, float* __restrict__ c,
                      float* __restrict__ zsOut, int step)
{
    int idx = blockIdx.x*256 + threadIdx.x;
    if (idx >= BB*DU) return;
    int b = idx / DU, u = idx % DU;
    float gi=0.f, gf=0.f, gg=0.f, go=0.f;
    const float* p = P + (size_t)b*4*DU + u;
    for (int s = 0; s < S; s++){
        gi += p[0]; gf += p[DU]; gg += p[2*DU]; go += p[3*DU];
        p += (size_t)BB*4*DU;
    }
    gi += bi[u]        + bh[u];
    gf += bi[DU+u]     + bh[DU+u];
    gg += bi[2*DU+u]   + bh[2*DU+u];
    go += bi[3*DU+u]   + bh[3*DU+u];
    float I = 1.f/(1.f+expf(-gi));
    float F = 1.f/(1.f+expf(-gf));
    float G = tanhf(gg);
    float O = 1.f/(1.f+expf(-go));
    float cn = F*c[idx] + I*G;
    c[idx] = cn;
    float hn = O*tanhf(cn);
    h[idx] = hn;
    if (zsOut) zsOut[((size_t)b*LP1 + step)*DU + u] = hn;
}

// ---------------- per-row log-softmax stats on logits -----------------------
__global__ void rowstats(const int* __restrict__ ys)
{
    const int r = blockIdx.x;
    const int b = r / LP1, l = r % LP1;
    const float* row = &g_logits[(size_t)r*OD];
    const int t = threadIdx.x;
    __shared__ float sm[256];
    __shared__ int   si[256];

    float mx = -1e30f; int mi = OD;
    for (int o = t; o < OD; o += 256){
        float v = row[o];
        if (v > mx){ mx = v; mi = o; }
    }
    sm[t] = mx; si[t] = mi; __syncthreads();
    for (int o = 128; o; o >>= 1){
        if (t < o){
            if (sm[t+o] > sm[t] || (sm[t+o] == sm[t] && si[t+o] < si[t])){
                sm[t] = sm[t+o]; si[t] = si[t+o];
            }
        }
        __syncthreads();
    }
    float M = sm[0]; int amax = si[0];
    __syncthreads();

    float s = 0.f;
    for (int o = t; o < OD; o += 256) s += expf(row[o] - M);
    sm[t] = s; __syncthreads();
    for (int o = 128; o; o >>= 1){ if (t < o) sm[t] += sm[t+o]; __syncthreads(); }
    if (t == 0){
        int tgt = (l < LL) ? ys[b*LL + l] : SOS_EOS;
        float lse = M + logf(sm[0]);
        g_nll[r]  = lse - row[tgt];
        g_corr[r] = (amax == tgt) ? 1 : 0;
    }
}

// ---------------- final reduction: loss, acc, ppl ---------------------------
__global__ void finalk(float* __restrict__ out)
{
    __shared__ double sd[256];
    __shared__ int    sc[256];
    const int t = threadIdx.x;
    double s = 0.0; int c = 0;
    for (int r = t; r < NROWS; r += 256){ s += (double)g_nll[r]; c += g_corr[r]; }
    sd[t] = s; sc[t] = c; __syncthreads();
    for (int o = 128; o; o >>= 1){ if (t < o){ sd[t]+=sd[t+o]; sc[t]+=sc[t+o]; } __syncthreads(); }
    if (t == 0){
        double loss = sd[0] / (double)NROWS * (double)LL;
        out[0] = (float)loss;
        out[1] = (float)((double)sc[0] / (double)NROWS);
        out[2] = (float)exp(loss / (double)BB);
    }
}

// ---------------- host orchestration ----------------------------------------
extern "C" void kernel_launch(void* const* d_in, const int* in_sizes, int n_in,
                              void* d_out, int out_size)
{
    const float* hs    = (const float*)d_in[0];
    const int*   hlens = (const int*)  d_in[1];
    const int*   ys    = (const int*)  d_in[2];
    const float* embed = (const float*)d_in[3];
    const float* Wenc  = (const float*)d_in[4];
    const float* benc  = (const float*)d_in[5];
    const float* Wdec  = (const float*)d_in[6];
    const float* Wih0  = (const float*)d_in[7];
    const float* Whh0  = (const float*)d_in[8];
    const float* bih0  = (const float*)d_in[9];
    const float* bhh0  = (const float*)d_in[10];
    const float* Wih1  = (const float*)d_in[11];
    const float* Whh1  = (const float*)d_in[12];
    const float* bih1  = (const float*)d_in[13];
    const float* bhh1  = (const float*)d_in[14];
    const float* Wout  = (const float*)d_in[15];
    const float* bout  = (const float*)d_in[16];
    float* out = (float*)d_out;

    float *pre, *zs, *logits, *z0, *c0, *z1, *c1, *attc, *decP, *g0P, *g1P;
    cudaGetSymbolAddress((void**)&pre,    g_pre);
    cudaGetSymbolAddress((void**)&zs,     g_zs);
    cudaGetSymbolAddress((void**)&logits, g_logits);
    cudaGetSymbolAddress((void**)&z0,     g_z0);
    cudaGetSymbolAddress((void**)&c0,     g_c0);
    cudaGetSymbolAddress((void**)&z1,     g_z1);
    cudaGetSymbolAddress((void**)&c1,     g_c1);
    cudaGetSymbolAddress((void**)&attc,   g_attc);
    cudaGetSymbolAddress((void**)&decP,   g_decP);
    cudaGetSymbolAddress((void**)&g0P,    g_g0P);
    cudaGetSymbolAddress((void**)&g1P,    g_g1P);

    initk<<<128,256>>>();

    // pre_enc = tanh(hs @ Wenc^T + benc):  M=16384, N=320, K=512
    gemm_big<<<dim3(5,128),256>>>(hs, Wenc, benc, pre, BB*TT, AD, EP, 1);

    for (int step = 0; step < LP1; step++){
        // dec partials: z0 @ Wdec^T  (N=320, K=1024, 2 k-slices of 512)
        gemm_small<<<dim3(3,2),256>>>(0, step, Wdec, Wdec, DU, DU, AD,
                                      embed, ys, attc, z0, z1, decP, 512);
        // attention (tanh+sum of dec partials, e, masked softmax, att_c)
        att_kernel<<<BB,512>>>(hs, hlens);
        // LSTM0 gates: [embed|att_c|z0] @ [Wih0|Whh0]^T  (K=2560, 10 slices)
        gemm_small<<<dim3(32,10),256>>>(1, step, Wih0, Whh0, DU+EP, DU, 4*DU,
                                        embed, ys, attc, z0, z1, g0P, 256);
        cellk<<<128,256>>>(g0P, 10, bih0, bhh0, z0, c0, (float*)0, 0);
        // LSTM1 gates: [z0|z1] @ [Wih1|Whh1]^T  (K=2048, 8 slices)
        gemm_small<<<dim3(32,8),256>>>(2, step, Wih1, Whh1, DU, DU, 4*DU,
                                       embed, ys, attc, z0, z1, g1P, 256);
        cellk<<<128,256>>>(g1P, 8, bih1, bhh1, z1, c1, zs, step);
    }

    // logits = zs @ Wout^T + bout:  M=4128, N=10000, K=1024
    gemm_big<<<dim3(157,33),256>>>(zs, Wout, bout, logits, NROWS, OD, DU, 0);
    rowstats<<<NROWS,256>>>(ys);
    finalk<<<1,256>>>(out);
    (void)in_sizes; (void)n_in; (void)out_size;
}

// round 13
// speedup vs baseline: 1.3891x; 1.3891x over previous
#include <cuda_runtime.h>
#include <math.h>

typedef unsigned long long ull;

#define BB 32
#define TT 512
#define EP 512
#define DU 1024
#define OD 10000
#define AD 320
#define LL 128
#define LP1 129
#define NROWS (BB*LP1)      /* 4128 */
#define SOS_EOS (OD-1)
#define DSPL 8              /* dec split-K slices */

// ---------------- scratch (device globals; no allocation allowed) ----------
__device__ float g_pre[(size_t)BB*TT*AD];       // tanh(hs @ Wenc^T + benc)  [B,T,A]
__device__ float g_zs[(size_t)BB*LP1*DU];       // z1 history               [B,L+1,DU]
__device__ float g_logits[(size_t)NROWS*OD];    // output logits
__device__ float g_z0[BB*DU];
__device__ float g_c0[BB*DU];
__device__ float g_z1[BB*DU];
__device__ float g_c1[BB*DU];
__device__ float g_attc[BB*EP];
__device__ float g_e[BB*TT];                    // attention scores per step
__device__ float g_decP[DSPL*BB*AD];            // dec partials (8 k-slices)
__device__ float g_g0P[10*BB*4*DU];             // gates0 partials (10 slices)
__device__ float g_g1P[8*BB*4*DU];              // gates1 partials (8 slices)
__device__ float g_nll[NROWS];
__device__ int   g_corr[NROWS];

// ---------------- packed f32x2 helpers (2x fp32 FMA throughput) ------------
__device__ __forceinline__ ull pk2(float lo, float hi){
    ull r; asm("mov.b64 %0, {%1, %2};" : "=l"(r) : "f"(lo), "f"(hi)); return r;
}
__device__ __forceinline__ void up2(ull v, float &lo, float &hi){
    asm("mov.b64 {%0, %1}, %2;" : "=f"(lo), "=f"(hi) : "l"(v));
}
__device__ __forceinline__ void fma2(ull &acc, ull a, ull b){
    asm("fma.rn.f32x2 %0, %1, %2, %0;" : "+l"(acc) : "l"(a), "l"(b));
}

// ---------------- init ------------------------------------------------------
__global__ void initk(){
    int i = blockIdx.x*256 + threadIdx.x;
    if (i < BB*DU){ g_z0[i]=0.f; g_c0[i]=0.f; g_z1[i]=0.f; g_c1[i]=0.f; }
}

// ---------------- big GEMM: C[M,N] = A[M,K] @ B[N,K]^T + bias, opt tanh ----
// BM=128, BN=64, BK=16, 256 threads, thread tile 8x4, f32x2 accumulation.
__global__ __launch_bounds__(256) void gemm_big(
    const float* __restrict__ A, const float* __restrict__ B,
    const float* __restrict__ bias, float* __restrict__ C,
    int M, int N, int K, int act)
{
    __shared__ float As[16][128];
    __shared__ float Bs[16][64];
    const int t  = threadIdx.x;
    const int m0 = blockIdx.y * 128;
    const int n0 = blockIdx.x * 64;
    const int mt = (t >> 4) * 8;
    const int nt = (t & 15) * 4;

    ull acc[8][2];
#pragma unroll
    for (int i = 0; i < 8; i++){ acc[i][0] = 0ULL; acc[i][1] = 0ULL; }

    for (int k0 = 0; k0 < K; k0 += 16){
#pragma unroll
        for (int l = 0; l < 2; l++){
            int idx = t + 256*l;
            int m = idx >> 2, q = idx & 3;
            float4 v = make_float4(0.f,0.f,0.f,0.f);
            int gm = m0 + m;
            if (gm < M) v = *(const float4*)(A + (size_t)gm*K + k0 + q*4);
            As[q*4+0][m]=v.x; As[q*4+1][m]=v.y; As[q*4+2][m]=v.z; As[q*4+3][m]=v.w;
        }
        {
            int n = t >> 2, q = t & 3;
            float4 v = make_float4(0.f,0.f,0.f,0.f);
            int gn = n0 + n;
            if (gn < N) v = *(const float4*)(B + (size_t)gn*K + k0 + q*4);
            Bs[q*4+0][n]=v.x; Bs[q*4+1][n]=v.y; Bs[q*4+2][n]=v.z; Bs[q*4+3][n]=v.w;
        }
        __syncthreads();
#pragma unroll
        for (int kk = 0; kk < 16; kk++){
            float4 a0 = *(const float4*)&As[kk][mt];
            float4 a1 = *(const float4*)&As[kk][mt+4];
            float4 b  = *(const float4*)&Bs[kk][nt];
            ull b01 = pk2(b.x, b.y), b23 = pk2(b.z, b.w);
            float av[8] = {a0.x,a0.y,a0.z,a0.w,a1.x,a1.y,a1.z,a1.w};
#pragma unroll
            for (int i = 0; i < 8; i++){
                ull a2 = pk2(av[i], av[i]);
                fma2(acc[i][0], a2, b01);
                fma2(acc[i][1], a2, b23);
            }
        }
        __syncthreads();
    }

    float bsv[4];
#pragma unroll
    for (int j = 0; j < 4; j++) bsv[j] = (n0+nt+j < N) ? bias[n0+nt+j] : 0.f;
#pragma unroll
    for (int i = 0; i < 8; i++){
        int gm = m0 + mt + i;
        if (gm >= M) continue;
        float v[4];
        up2(acc[i][0], v[0], v[1]);
        up2(acc[i][1], v[2], v[3]);
#pragma unroll
        for (int j = 0; j < 4; j++){
            int gn = n0 + nt + j;
            if (gn < N){
                float r = v[j] + bsv[j];
                if (act) r = tanhf(r);
                C[(size_t)gm*N + gn] = r;
            }
        }
    }
}

// ---------------- small-M GEMM (M=32) with split-K partial output ----------
// C_partial[s][32][N] = A[32, kslice] @ B[N, kslice]^T ; B split into B1|B2 at K1.
// A is gathered per mode: 0: z0 ; 1: [embed(ys_in[step]) | att_c | z0] ; 2: [z0 | z1]
__global__ __launch_bounds__(256) void gemm_small(
    int mode, int step,
    const float* __restrict__ B1, const float* __restrict__ B2,
    int K1, int K2, int N,
    const float* __restrict__ embed, const int* __restrict__ ys,
    const float* __restrict__ attc,
    const float* __restrict__ x0, const float* __restrict__ x1,
    float* __restrict__ P, int kPerSplit)
{
    __shared__ float As[32*32];    // [k][b]
    __shared__ float Bs[32*128];   // [k][n]
    const int t    = threadIdx.x;
    const int n0   = blockIdx.x * 128;
    const int s    = blockIdx.y;
    const int kbeg = s * kPerSplit;
    const int kend = kbeg + kPerSplit;
    const int nt = (t & 31) * 4;
    const int bt = (t >> 5) * 4;
    const int lb = t >> 3;     // batch row this thread loads (A)
    const int lq = t & 7;      // k-quad

    ull acc[4][2];
#pragma unroll
    for (int i = 0; i < 4; i++){ acc[i][0]=0ULL; acc[i][1]=0ULL; }

    for (int k0 = kbeg; k0 < kend; k0 += 32){
        {   // A tile: 32b x 32k, one float4 per thread, gather by mode
            int kg = k0 + lq*4;
            const float* src;
            if (mode == 1){
                if (kg < DU){
                    int tok = (step == 0) ? SOS_EOS : ys[lb*LL + step - 1];
                    src = embed + (size_t)tok*DU + kg;
                } else if (kg < DU + EP){
                    src = attc + lb*EP + (kg - DU);
                } else {
                    src = x0 + lb*DU + (kg - DU - EP);
                }
            } else if (mode == 2){
                src = (kg < DU) ? (x0 + lb*DU + kg) : (x1 + lb*DU + (kg - DU));
            } else {
                src = x0 + lb*DU + kg;
            }
            float4 v = *(const float4*)src;
            As[(lq*4+0)*32+lb]=v.x; As[(lq*4+1)*32+lb]=v.y;
            As[(lq*4+2)*32+lb]=v.z; As[(lq*4+3)*32+lb]=v.w;
        }
#pragma unroll
        for (int l = 0; l < 4; l++){   // B tile: 128n x 32k
            int idx = t + 256*l;
            int n = idx >> 3, q = idx & 7;
            int gn = n0 + n, kg = k0 + q*4;
            float4 v = make_float4(0.f,0.f,0.f,0.f);
            if (gn < N){
                v = (kg < K1) ? *(const float4*)(B1 + (size_t)gn*K1 + kg)
                              : *(const float4*)(B2 + (size_t)gn*K2 + (kg - K1));
            }
            Bs[(q*4+0)*128+n]=v.x; Bs[(q*4+1)*128+n]=v.y;
            Bs[(q*4+2)*128+n]=v.z; Bs[(q*4+3)*128+n]=v.w;
        }
        __syncthreads();
#pragma unroll
        for (int kk = 0; kk < 32; kk++){
            float4 a = *(const float4*)&As[kk*32 + bt];
            float4 b = *(const float4*)&Bs[kk*128 + nt];
            ull b01 = pk2(b.x,b.y), b23 = pk2(b.z,b.w);
            float av[4] = {a.x,a.y,a.z,a.w};
#pragma unroll
            for (int i = 0; i < 4; i++){
                ull a2 = pk2(av[i], av[i]);
                fma2(acc[i][0], a2, b01);
                fma2(acc[i][1], a2, b23);
            }
        }
        __syncthreads();
    }

#pragma unroll
    for (int i = 0; i < 4; i++){
        int b = bt + i;
        float v[4];
        up2(acc[i][0], v[0], v[1]);
        up2(acc[i][1], v[2], v[3]);
        int gn = n0 + nt;
        if (gn + 3 < N){
            *(float4*)(P + ((size_t)s*BB + b)*N + gn) = make_float4(v[0],v[1],v[2],v[3]);
        } else {
#pragma unroll
            for (int j = 0; j < 4; j++)
                if (gn + j < N) P[((size_t)s*BB + b)*N + gn + j] = v[j];
        }
    }
}

// ---------------- attention phase A: dec reduce+tanh, e = pre . dec ---------
// grid (B, 8): block (b, ts) computes e[b, ts*64 .. ts*64+64)
__global__ __launch_bounds__(256) void attA_kernel()
{
    const int b  = blockIdx.x;
    const int ts = blockIdx.y;
    const int t  = threadIdx.x;
    __shared__ float dec_s[AD];

    for (int a = t; a < AD; a += 256){
        float sv = 0.f;
#pragma unroll
        for (int s = 0; s < DSPL; s++) sv += g_decP[((size_t)s*BB + b)*AD + a];
        dec_s[a] = tanhf(sv);
    }
    __syncthreads();

    const int warp = t >> 5, lane = t & 31;
    const float* pr = &g_pre[((size_t)b*TT + (size_t)ts*64)*AD];
#pragma unroll
    for (int r = warp; r < 64; r += 8){
        const float* p = pr + (size_t)r*AD;
        float sv = 0.f;
        for (int a = lane; a < AD; a += 32) sv += p[a]*dec_s[a];
#pragma unroll
        for (int o = 16; o; o >>= 1) sv += __shfl_xor_sync(0xffffffffu, sv, o);
        if (lane == 0) g_e[b*TT + ts*64 + r] = sv;
    }
}

// ---------------- attention phase C: softmax (per-block) + att_c d-slice ----
// grid (B, 4), 128 threads: block (b, dt) computes att_c[b, dt*128 .. +128)
__global__ __launch_bounds__(128) void attC_kernel(
    const float* __restrict__ hs, const int* __restrict__ hlens)
{
    const int b  = blockIdx.x;
    const int dt = blockIdx.y;
    const int t  = threadIdx.x;
    __shared__ float red[128];
    __shared__ float w_s[TT];

    const int hlen = hlens[b];
    const float* eb = &g_e[b*TT];
    float v[4];
#pragma unroll
    for (int j = 0; j < 4; j++){
        int tt = t + j*128;
        v[j] = (tt < hlen) ? 2.f*eb[tt] : -1e10f;
    }
    float mv = fmaxf(fmaxf(v[0],v[1]), fmaxf(v[2],v[3]));
    red[t] = mv; __syncthreads();
    for (int o = 64; o; o >>= 1){ if (t < o) red[t] = fmaxf(red[t], red[t+o]); __syncthreads(); }
    float mx = red[0]; __syncthreads();

    float ex[4]; float sm = 0.f;
#pragma unroll
    for (int j = 0; j < 4; j++){ ex[j] = expf(v[j]-mx); sm += ex[j]; }
    red[t] = sm; __syncthreads();
    for (int o = 64; o; o >>= 1){ if (t < o) red[t] += red[t+o]; __syncthreads(); }
    float inv = 1.f / red[0];
    __syncthreads();
#pragma unroll
    for (int j = 0; j < 4; j++) w_s[t + j*128] = ex[j]*inv;
    __syncthreads();

    // att_c[b, d] = sum_t w[t]*hs[b,t,d] ; d = dt*128 + t (one d per thread)
    const int d = dt*128 + t;
    const float* hb = hs + (size_t)b*TT*EP + d;
    float a0=0.f, a1=0.f, a2=0.f, a3=0.f;
#pragma unroll 4
    for (int tt = 0; tt < TT; tt += 4){
        a0 += w_s[tt+0]*hb[(size_t)(tt+0)*EP];
        a1 += w_s[tt+1]*hb[(size_t)(tt+1)*EP];
        a2 += w_s[tt+2]*hb[(size_t)(tt+2)*EP];
        a3 += w_s[tt+3]*hb[(size_t)(tt+3)*EP];
    }
    g_attc[b*EP + d] = (a0+a1) + (a2+a3);
}

// ---------------- LSTM cell: reduce split-K partials + biases, gate math ----
__global__ void cellk(const float* __restrict__ P, int S,
                      const float* __restrict__ bi, const float* __restrict__ bh,
                      float* __restrict__ h, float* __restrict__ c,
                      float* __restrict__ zsOut, int step)
{
    int idx = blockIdx.x*256 + threadIdx.x;
    if (idx >= BB*DU) return;
    int b = idx / DU, u = idx % DU;
    float gi=0.f, gf=0.f, gg=0.f, go=0.f;
    const float* p = P + (size_t)b*4*DU + u;
    for (int s = 0; s < S; s++){
        gi += p[0]; gf += p[DU]; gg += p[2*DU]; go += p[3*DU];
        p += (size_t)BB*4*DU;
    }
    gi += bi[u]        + bh[u];
    gf += bi[DU+u]     + bh[DU+u];
    gg += bi[2*DU+u]   + bh[2*DU+u];
    go += bi[3*DU+u]   + bh[3*DU+u];
    float I = 1.f/(1.f+expf(-gi));
    float F = 1.f/(1.f+expf(-gf));
    float G = tanhf(gg);
    float O = 1.f/(1.f+expf(-go));
    float cn = F*c[idx] + I*G;
    c[idx] = cn;
    float hn = O*tanhf(cn);
    h[idx] = hn;
    if (zsOut) zsOut[((size_t)b*LP1 + step)*DU + u] = hn;
}

// ---------------- per-row log-softmax stats on logits -----------------------
__global__ void rowstats(const int* __restrict__ ys)
{
    const int r = blockIdx.x;
    const int b = r / LP1, l = r % LP1;
    const float* row = &g_logits[(size_t)r*OD];
    const int t = threadIdx.x;
    __shared__ float sm[256];
    __shared__ int   si[256];

    float mx = -1e30f; int mi = OD;
    for (int o = t; o < OD; o += 256){
        float v = row[o];
        if (v > mx){ mx = v; mi = o; }
    }
    sm[t] = mx; si[t] = mi; __syncthreads();
    for (int o = 128; o; o >>= 1){
        if (t < o){
            if (sm[t+o] > sm[t] || (sm[t+o] == sm[t] && si[t+o] < si[t])){
                sm[t] = sm[t+o]; si[t] = si[t+o];
            }
        }
        __syncthreads();
    }
    float M = sm[0]; int amax = si[0];
    __syncthreads();

    float s = 0.f;
    for (int o = t; o < OD; o += 256) s += expf(row[o] - M);
    sm[t] = s; __syncthreads();
    for (int o = 128; o; o >>= 1){ if (t < o) sm[t] += sm[t+o]; __syncthreads(); }
    if (t == 0){
        int tgt = (l < LL) ? ys[b*LL + l] : SOS_EOS;
        float lse = M + logf(sm[0]);
        g_nll[r]  = lse - row[tgt];
        g_corr[r] = (amax == tgt) ? 1 : 0;
    }
}

// ---------------- final reduction: loss, acc, ppl ---------------------------
__global__ void finalk(float* __restrict__ out)
{
    __shared__ double sd[256];
    __shared__ int    sc[256];
    const int t = threadIdx.x;
    double s = 0.0; int c = 0;
    for (int r = t; r < NROWS; r += 256){ s += (double)g_nll[r]; c += g_corr[r]; }
    sd[t] = s; sc[t] = c; __syncthreads();
    for (int o = 128; o; o >>= 1){ if (t < o){ sd[t]+=sd[t+o]; sc[t]+=sc[t+o]; } __syncthreads(); }
    if (t == 0){
        double loss = sd[0] / (double)NROWS * (double)LL;
        out[0] = (float)loss;
        out[1] = (float)((double)sc[0] / (double)NROWS);
        out[2] = (float)exp(loss / (double)BB);
    }
}

// ---------------- host orchestration ----------------------------------------
extern "C" void kernel_launch(void* const* d_in, const int* in_sizes, int n_in,
                              void* d_out, int out_size)
{
    const float* hs    = (const float*)d_in[0];
    const int*   hlens = (const int*)  d_in[1];
    const int*   ys    = (const int*)  d_in[2];
    const float* embed = (const float*)d_in[3];
    const float* Wenc  = (const float*)d_in[4];
    const float* benc  = (const float*)d_in[5];
    const float* Wdec  = (const float*)d_in[6];
    const float* Wih0  = (const float*)d_in[7];
    const float* Whh0  = (const float*)d_in[8];
    const float* bih0  = (const float*)d_in[9];
    const float* bhh0  = (const float*)d_in[10];
    const float* Wih1  = (const float*)d_in[11];
    const float* Whh1  = (const float*)d_in[12];
    const float* bih1  = (const float*)d_in[13];
    const float* bhh1  = (const float*)d_in[14];
    const float* Wout  = (const float*)d_in[15];
    const float* bout  = (const float*)d_in[16];
    float* out = (float*)d_out;

    float *pre, *zs, *logits, *z0, *c0, *z1, *c1, *attc, *decP, *g0P, *g1P;
    cudaGetSymbolAddress((void**)&pre,    g_pre);
    cudaGetSymbolAddress((void**)&zs,     g_zs);
    cudaGetSymbolAddress((void**)&logits, g_logits);
    cudaGetSymbolAddress((void**)&z0,     g_z0);
    cudaGetSymbolAddress((void**)&c0,     g_c0);
    cudaGetSymbolAddress((void**)&z1,     g_z1);
    cudaGetSymbolAddress((void**)&c1,     g_c1);
    cudaGetSymbolAddress((void**)&attc,   g_attc);
    cudaGetSymbolAddress((void**)&decP,   g_decP);
    cudaGetSymbolAddress((void**)&g0P,    g_g0P);
    cudaGetSymbolAddress((void**)&g1P,    g_g1P);

    initk<<<128,256>>>();

    // pre_enc = tanh(hs @ Wenc^T + benc):  M=16384, N=320, K=512
    gemm_big<<<dim3(5,128),256>>>(hs, Wenc, benc, pre, BB*TT, AD, EP, 1);

    for (int step = 0; step < LP1; step++){
        // dec partials: z0 @ Wdec^T  (N=320, K=1024, 8 k-slices of 128)
        gemm_small<<<dim3(3,DSPL),256>>>(0, step, Wdec, Wdec, DU, DU, AD,
                                         embed, ys, attc, z0, z1, decP, 128);
        // attention A: dec reduce+tanh, e-scores  (256 blocks)
        attA_kernel<<<dim3(BB,8),256>>>();
        // attention C: per-block softmax + att_c d-slices (128 blocks)
        attC_kernel<<<dim3(BB,4),128>>>(hs, hlens);
        // LSTM0 gates: [embed|att_c|z0] @ [Wih0|Whh0]^T  (K=2560, 10 slices)
        gemm_small<<<dim3(32,10),256>>>(1, step, Wih0, Whh0, DU+EP, DU, 4*DU,
                                        embed, ys, attc, z0, z1, g0P, 256);
        cellk<<<128,256>>>(g0P, 10, bih0, bhh0, z0, c0, (float*)0, 0);
        // LSTM1 gates: [z0|z1] @ [Wih1|Whh1]^T  (K=2048, 8 slices)
        gemm_small<<<dim3(32,8),256>>>(2, step, Wih1, Whh1, DU, DU, 4*DU,
                                       embed, ys, attc, z0, z1, g1P, 256);
        cellk<<<128,256>>>(g1P, 8, bih1, bhh1, z1, c1, zs, step);
    }

    // logits = zs @ Wout^T + bout:  M=4128, N=10000, K=1024
    gemm_big<<<dim3(157,33),256>>>(zs, Wout, bout, logits, NROWS, OD, DU, 0);
    rowstats<<<NROWS,256>>>(ys);
    finalk<<<1,256>>>(out);
    (void)in_sizes; (void)n_in; (void)out_size;
}

// round 15
// speedup vs baseline: 2.0705x; 1.4905x over previous
#include <cuda_runtime.h>
#include <math.h>

typedef unsigned long long ull;

#define BB 32
#define TT 512
#define EP 512
#define DU 1024
#define OD 10000
#define AD 320
#define LL 128
#define LP1 129
#define NROWS (BB*LP1)      /* 4128 */
#define SOS_EOS (OD-1)
#define DSPL 16             /* dec split-K slices */

// ---------------- scratch (device globals; no allocation allowed) ----------
__device__ float g_pre[(size_t)BB*TT*AD];       // tanh(hs @ Wenc^T + benc)
__device__ float g_zs[(size_t)BB*LP1*DU];       // z1 history
__device__ float g_logits[(size_t)NROWS*OD];
__device__ float g_z0[BB*DU];
__device__ float g_c0[BB*DU];
__device__ float g_z1[BB*DU];
__device__ float g_c1[BB*DU];
__device__ float g_attc[BB*EP];
__device__ float g_e[BB*TT];
__device__ float g_decP[DSPL*BB*AD];            // dec partials
__device__ float g_g0P[8*BB*4*DU];              // gates0 partials (8 slices)
__device__ float g_g1P[8*BB*4*DU];              // gates1 partials (8 slices)
__device__ float g_nll[NROWS];
__device__ int   g_corr[NROWS];
// transposed (k-major) weights, built once per call
__device__ float g_g0Wt[(size_t)2560*4096];     // rows: [Wih0 k<1536 | Whh0]
__device__ float g_g1Wt[(size_t)2048*4096];     // rows: [Wih1 k<1024 | Whh1]
__device__ float g_decWt[(size_t)1024*512];     // Wdec^T padded to 512 cols

// ---------------- packed f32x2 helpers -------------------------------------
__device__ __forceinline__ ull pk2(float lo, float hi){
    ull r; asm("mov.b64 %0, {%1, %2};" : "=l"(r) : "f"(lo), "f"(hi)); return r;
}
__device__ __forceinline__ void up2(ull v, float &lo, float &hi){
    asm("mov.b64 {%0, %1}, %2;" : "=f"(lo), "=f"(hi) : "l"(v));
}
__device__ __forceinline__ void fma2(ull &acc, ull a, ull b){
    asm("fma.rn.f32x2 %0, %1, %2, %0;" : "+l"(acc) : "l"(a), "l"(b));
}
// ---------------- cp.async helpers ------------------------------------------
__device__ __forceinline__ void cpa16(void* dst, const void* src){
    unsigned d = (unsigned)__cvta_generic_to_shared(dst);
    asm volatile("cp.async.cg.shared.global [%0], [%1], 16;" :: "r"(d), "l"(src));
}
__device__ __forceinline__ void cpa_commit(){ asm volatile("cp.async.commit_group;"); }
__device__ __forceinline__ void cpa_wait0(){ asm volatile("cp.async.wait_group 0;" ::: "memory"); }

// ---------------- init ------------------------------------------------------
__global__ void initk(){
    int i = blockIdx.x*256 + threadIdx.x;
    if (i < BB*DU){ g_z0[i]=0.f; g_c0[i]=0.f; g_z1[i]=0.f; g_c1[i]=0.f; }
    if (i < 1024*512) g_decWt[i] = 0.f;
}

// ---------------- weight transpose: Wt[kofs+k][n] = W[n][k] -----------------
__global__ __launch_bounds__(256) void transpose_k(
    const float* __restrict__ W, float* __restrict__ Wt,
    int rows, int cols, int ldt, int kofs)
{
    __shared__ float tile[32][33];
    int c0 = blockIdx.x*32, r0 = blockIdx.y*32;
    int x = threadIdx.x & 31, y = threadIdx.x >> 5;
#pragma unroll
    for (int j = 0; j < 4; j++){
        int r = r0 + y + j*8;
        if (r < rows && c0 + x < cols)
            tile[y+j*8][x] = W[(size_t)r*cols + c0 + x];
    }
    __syncthreads();
#pragma unroll
    for (int j = 0; j < 4; j++){
        int k = c0 + y + j*8, n = r0 + x;
        if (k < cols && n < rows)
            Wt[(size_t)(kofs + k)*ldt + n] = tile[x][y+j*8];
    }
}

// ---------------- big GEMM: C[M,N] = A[M,K] @ B[N,K]^T + bias, opt tanh ----
__global__ __launch_bounds__(256) void gemm_big(
    const float* __restrict__ A, const float* __restrict__ B,
    const float* __restrict__ bias, float* __restrict__ C,
    int M, int N, int K, int act)
{
    __shared__ float As[16][128];
    __shared__ float Bs[16][64];
    const int t  = threadIdx.x;
    const int m0 = blockIdx.y * 128;
    const int n0 = blockIdx.x * 64;
    const int mt = (t >> 4) * 8;
    const int nt = (t & 15) * 4;

    ull acc[8][2];
#pragma unroll
    for (int i = 0; i < 8; i++){ acc[i][0] = 0ULL; acc[i][1] = 0ULL; }

    for (int k0 = 0; k0 < K; k0 += 16){
#pragma unroll
        for (int l = 0; l < 2; l++){
            int idx = t + 256*l;
            int m = idx >> 2, q = idx & 3;
            float4 v = make_float4(0.f,0.f,0.f,0.f);
            int gm = m0 + m;
            if (gm < M) v = *(const float4*)(A + (size_t)gm*K + k0 + q*4);
            As[q*4+0][m]=v.x; As[q*4+1][m]=v.y; As[q*4+2][m]=v.z; As[q*4+3][m]=v.w;
        }
        {
            int n = t >> 2, q = t & 3;
            float4 v = make_float4(0.f,0.f,0.f,0.f);
            int gn = n0 + n;
            if (gn < N) v = *(const float4*)(B + (size_t)gn*K + k0 + q*4);
            Bs[q*4+0][n]=v.x; Bs[q*4+1][n]=v.y; Bs[q*4+2][n]=v.z; Bs[q*4+3][n]=v.w;
        }
        __syncthreads();
#pragma unroll
        for (int kk = 0; kk < 16; kk++){
            float4 a0 = *(const float4*)&As[kk][mt];
            float4 a1 = *(const float4*)&As[kk][mt+4];
            float4 b  = *(const float4*)&Bs[kk][nt];
            ull b01 = pk2(b.x, b.y), b23 = pk2(b.z, b.w);
            float av[8] = {a0.x,a0.y,a0.z,a0.w,a1.x,a1.y,a1.z,a1.w};
#pragma unroll
            for (int i = 0; i < 8; i++){
                ull a2 = pk2(av[i], av[i]);
                fma2(acc[i][0], a2, b01);
                fma2(acc[i][1], a2, b23);
            }
        }
        __syncthreads();
    }

    float bsv[4];
#pragma unroll
    for (int j = 0; j < 4; j++) bsv[j] = (n0+nt+j < N) ? bias[n0+nt+j] : 0.f;
#pragma unroll
    for (int i = 0; i < 8; i++){
        int gm = m0 + mt + i;
        if (gm >= M) continue;
        float v[4];
        up2(acc[i][0], v[0], v[1]);
        up2(acc[i][1], v[2], v[3]);
#pragma unroll
        for (int j = 0; j < 4; j++){
            int gn = n0 + nt + j;
            if (gn < N){
                float r = v[j] + bsv[j];
                if (act) r = tanhf(r);
                C[(size_t)gm*N + gn] = r;
            }
        }
    }
}

// ---------------- recurrent small-M GEMM v3 ---------------------------------
// P[s][32][N] += A[32, kslice] @ Wt[kslice, N]  (Wt k-major, row stride ldw)
// 128 threads, tile 8b x 8n, N=256 per block, BK=16, cp.async double buffer.
// A gathered per mode: 0: z0 ; 1: [embed | att_c | z0] ; 2: [z0 | z1]
__global__ __launch_bounds__(128) void gemm_small3(
    int mode, int step, const float* __restrict__ Wt, int ldw, int N,
    const float* __restrict__ embed, const int* __restrict__ ys,
    const float* __restrict__ attc, const float* __restrict__ x0,
    const float* __restrict__ x1, float* __restrict__ P, int kPerSplit)
{
    __shared__ __align__(16) float As[2][16][32];
    __shared__ __align__(16) float Bs[2][16][256];
    const int t    = threadIdx.x;
    const int warp = t >> 5, lane = t & 31;
    const int bt   = warp*8;
    const int nt   = lane*4;
    const int n0   = blockIdx.x*256;
    const int s    = blockIdx.y;
    const int kbeg = s*kPerSplit;
    const int NK   = kPerSplit >> 4;
    const int ab   = t >> 2;      // A-load: batch row
    const int akq  = t & 3;       // A-load: k-quad

    ull acc[8][4];
#pragma unroll
    for (int i = 0; i < 8; i++)
#pragma unroll
        for (int j = 0; j < 4; j++) acc[i][j] = 0ULL;

    // ---- A gather (k-contiguous float4 for row ab at k-offset)
    auto loadA = [&](int it) -> float4 {
        int kg = kbeg + it*16 + akq*4;
        const float* src;
        if (mode == 1){
            if (kg < DU){
                int tok = (step == 0) ? SOS_EOS : ys[ab*LL + step - 1];
                src = embed + (size_t)tok*DU + kg;
            } else if (kg < DU + EP){
                src = attc + ab*EP + (kg - DU);
            } else {
                src = x0 + ab*DU + (kg - DU - EP);
            }
        } else if (mode == 2){
            src = (kg < DU) ? (x0 + ab*DU + kg) : (x1 + ab*DU + (kg - DU));
        } else {
            src = x0 + ab*DU + kg;
        }
        return *(const float4*)src;
    };

    // ---- prologue: B tile 0 via cp.async, A tile 0 via regs
    {
#pragma unroll
        for (int l = 0; l < 8; l++){
            int idx = l*128 + t;
            int row = idx >> 6, c4 = idx & 63;
            cpa16(&Bs[0][row][c4*4],
                  Wt + (size_t)(kbeg + row)*ldw + n0 + c4*4);
        }
        cpa_commit();
        float4 ra = loadA(0);
        cpa_wait0();
        As[0][akq*4+0][ab] = ra.x;
        As[0][akq*4+1][ab] = ra.y;
        As[0][akq*4+2][ab] = ra.z;
        As[0][akq*4+3][ab] = ra.w;
        __syncthreads();
    }

    for (int it = 0; it < NK; it++){
        const int buf = it & 1, nb = buf ^ 1;
        float4 ra;
        const bool pf = (it + 1 < NK);
        if (pf){
            int krow = kbeg + (it+1)*16;
#pragma unroll
            for (int l = 0; l < 8; l++){
                int idx = l*128 + t;
                int row = idx >> 6, c4 = idx & 63;
                cpa16(&Bs[nb][row][c4*4],
                      Wt + (size_t)(krow + row)*ldw + n0 + c4*4);
            }
            cpa_commit();
            ra = loadA(it+1);
        }
        // ---- compute on buf
#pragma unroll
        for (int kk = 0; kk < 16; kk++){
            float4 a0 = *(const float4*)&As[buf][kk][bt];
            float4 a1 = *(const float4*)&As[buf][kk][bt+4];
            float4 b0 = *(const float4*)&Bs[buf][kk][nt];
            float4 b1 = *(const float4*)&Bs[buf][kk][nt+128];
            ull p0 = pk2(b0.x,b0.y), p1 = pk2(b0.z,b0.w);
            ull p2 = pk2(b1.x,b1.y), p3 = pk2(b1.z,b1.w);
            float av[8] = {a0.x,a0.y,a0.z,a0.w,a1.x,a1.y,a1.z,a1.w};
#pragma unroll
            for (int i = 0; i < 8; i++){
                ull ad = pk2(av[i], av[i]);
                fma2(acc[i][0], ad, p0);
                fma2(acc[i][1], ad, p1);
                fma2(acc[i][2], ad, p2);
                fma2(acc[i][3], ad, p3);
            }
        }
        __syncthreads();
        if (pf){
            cpa_wait0();
            As[nb][akq*4+0][ab] = ra.x;
            As[nb][akq*4+1][ab] = ra.y;
            As[nb][akq*4+2][ab] = ra.z;
            As[nb][akq*4+3][ab] = ra.w;
        }
        __syncthreads();
    }

    // ---- epilogue: store partials (guard N for dec)
#pragma unroll
    for (int i = 0; i < 8; i++){
        int b = bt + i;
        float v[8];
        up2(acc[i][0], v[0], v[1]); up2(acc[i][1], v[2], v[3]);
        up2(acc[i][2], v[4], v[5]); up2(acc[i][3], v[6], v[7]);
        size_t base = ((size_t)s*BB + b)*(size_t)N;
        int c = n0 + nt;
        if (c + 3 < N)
            *(float4*)&P[base + c] = make_float4(v[0],v[1],v[2],v[3]);
        else {
#pragma unroll
            for (int j = 0; j < 4; j++) if (c + j < N) P[base + c + j] = v[j];
        }
        c = n0 + 128 + nt;
        if (c + 3 < N)
            *(float4*)&P[base + c] = make_float4(v[4],v[5],v[6],v[7]);
        else {
#pragma unroll
            for (int j = 0; j < 4; j++) if (c + j < N) P[base + c + j] = v[4+j];
        }
    }
}

// ---------------- attention phase A: dec reduce+tanh, e = pre . dec ---------
__global__ __launch_bounds__(256) void attA_kernel()
{
    const int b  = blockIdx.x;
    const int ts = blockIdx.y;
    const int t  = threadIdx.x;
    __shared__ float dec_s[AD];

    for (int a = t; a < AD; a += 256){
        float sv = 0.f;
#pragma unroll
        for (int s = 0; s < DSPL; s++) sv += g_decP[((size_t)s*BB + b)*AD + a];
        dec_s[a] = tanhf(sv);
    }
    __syncthreads();

    const int warp = t >> 5, lane = t & 31;
    const float* pr = &g_pre[((size_t)b*TT + (size_t)ts*64)*AD];
#pragma unroll
    for (int r = warp; r < 64; r += 8){
        const float* p = pr + (size_t)r*AD;
        float sv = 0.f;
        for (int a = lane; a < AD; a += 32) sv += p[a]*dec_s[a];
#pragma unroll
        for (int o = 16; o; o >>= 1) sv += __shfl_xor_sync(0xffffffffu, sv, o);
        if (lane == 0) g_e[b*TT + ts*64 + r] = sv;
    }
}

// ---------------- attention phase C: softmax + att_c d-slice ----------------
__global__ __launch_bounds__(128) void attC_kernel(
    const float* __restrict__ hs, const int* __restrict__ hlens)
{
    const int b  = blockIdx.x;
    const int dt = blockIdx.y;
    const int t  = threadIdx.x;
    __shared__ float red[128];
    __shared__ float w_s[TT];

    const int hlen = hlens[b];
    const float* eb = &g_e[b*TT];
    float v[4];
#pragma unroll
    for (int j = 0; j < 4; j++){
        int tt = t + j*128;
        v[j] = (tt < hlen) ? 2.f*eb[tt] : -1e10f;
    }
    float mv = fmaxf(fmaxf(v[0],v[1]), fmaxf(v[2],v[3]));
    red[t] = mv; __syncthreads();
    for (int o = 64; o; o >>= 1){ if (t < o) red[t] = fmaxf(red[t], red[t+o]); __syncthreads(); }
    float mx = red[0]; __syncthreads();

    float ex[4]; float sm = 0.f;
#pragma unroll
    for (int j = 0; j < 4; j++){ ex[j] = expf(v[j]-mx); sm += ex[j]; }
    red[t] = sm; __syncthreads();
    for (int o = 64; o; o >>= 1){ if (t < o) red[t] += red[t+o]; __syncthreads(); }
    float inv = 1.f / red[0];
    __syncthreads();
#pragma unroll
    for (int j = 0; j < 4; j++) w_s[t + j*128] = ex[j]*inv;
    __syncthreads();

    const int d = dt*128 + t;
    const float* hb = hs + (size_t)b*TT*EP + d;
    float a0=0.f, a1=0.f, a2=0.f, a3=0.f;
#pragma unroll 4
    for (int tt = 0; tt < TT; tt += 4){
        a0 += w_s[tt+0]*hb[(size_t)(tt+0)*EP];
        a1 += w_s[tt+1]*hb[(size_t)(tt+1)*EP];
        a2 += w_s[tt+2]*hb[(size_t)(tt+2)*EP];
        a3 += w_s[tt+3]*hb[(size_t)(tt+3)*EP];
    }
    g_attc[b*EP + d] = (a0+a1) + (a2+a3);
}

// ---------------- LSTM cell: reduce split-K partials + biases, gate math ----
__global__ void cellk(const float* __restrict__ P, int S,
                      const float* __restrict__ bi, const float* __restrict__ bh,
                      float* __restrict__ h, float* __restrict__ c,
                      float* __restrict__ zsOut, int step)
{
    int idx = blockIdx.x*256 + threadIdx.x;
    if (idx >= BB*DU) return;
    int b = idx / DU, u = idx % DU;
    float gi=0.f, gf=0.f, gg=0.f, go=0.f;
    const float* p = P + (size_t)b*4*DU + u;
    for (int s = 0; s < S; s++){
        gi += p[0]; gf += p[DU]; gg += p[2*DU]; go += p[3*DU];
        p += (size_t)BB*4*DU;
    }
    gi += bi[u]        + bh[u];
    gf += bi[DU+u]     + bh[DU+u];
    gg += bi[2*DU+u]   + bh[2*DU+u];
    go += bi[3*DU+u]   + bh[3*DU+u];
    float I = 1.f/(1.f+expf(-gi));
    float F = 1.f/(1.f+expf(-gf));
    float G = tanhf(gg);
    float O = 1.f/(1.f+expf(-go));
    float cn = F*c[idx] + I*G;
    c[idx] = cn;
    float hn = O*tanhf(cn);
    h[idx] = hn;
    if (zsOut) zsOut[((size_t)b*LP1 + step)*DU + u] = hn;
}

// ---------------- per-row log-softmax stats on logits -----------------------
__global__ void rowstats(const int* __restrict__ ys)
{
    const int r = blockIdx.x;
    const int b = r / LP1, l = r % LP1;
    const float* row = &g_logits[(size_t)r*OD];
    const int t = threadIdx.x;
    __shared__ float sm[256];
    __shared__ int   si[256];

    float mx = -1e30f; int mi = OD;
    for (int o = t; o < OD; o += 256){
        float v = row[o];
        if (v > mx){ mx = v; mi = o; }
    }
    sm[t] = mx; si[t] = mi; __syncthreads();
    for (int o = 128; o; o >>= 1){
        if (t < o){
            if (sm[t+o] > sm[t] || (sm[t+o] == sm[t] && si[t+o] < si[t])){
                sm[t] = sm[t+o]; si[t] = si[t+o];
            }
        }
        __syncthreads();
    }
    float M = sm[0]; int amax = si[0];
    __syncthreads();

    float s = 0.f;
    for (int o = t; o < OD; o += 256) s += expf(row[o] - M);
    sm[t] = s; __syncthreads();
    for (int o = 128; o; o >>= 1){ if (t < o) sm[t] += sm[t+o]; __syncthreads(); }
    if (t == 0){
        int tgt = (l < LL) ? ys[b*LL + l] : SOS_EOS;
        float lse = M + logf(sm[0]);
        g_nll[r]  = lse - row[tgt];
        g_corr[r] = (amax == tgt) ? 1 : 0;
    }
}

// ---------------- final reduction: loss, acc, ppl ---------------------------
__global__ void finalk(float* __restrict__ out)
{
    __shared__ double sd[256];
    __shared__ int    sc[256];
    const int t = threadIdx.x;
    double s = 0.0; int c = 0;
    for (int r = t; r < NROWS; r += 256){ s += (double)g_nll[r]; c += g_corr[r]; }
    sd[t] = s; sc[t] = c; __syncthreads();
    for (int o = 128; o; o >>= 1){ if (t < o){ sd[t]+=sd[t+o]; sc[t]+=sc[t+o]; } __syncthreads(); }
    if (t == 0){
        double loss = sd[0] / (double)NROWS * (double)LL;
        out[0] = (float)loss;
        out[1] = (float)((double)sc[0] / (double)NROWS);
        out[2] = (float)exp(loss / (double)BB);
    }
}

// ---------------- host orchestration ----------------------------------------
extern "C" void kernel_launch(void* const* d_in, const int* in_sizes, int n_in,
                              void* d_out, int out_size)
{
    const float* hs    = (const float*)d_in[0];
    const int*   hlens = (const int*)  d_in[1];
    const int*   ys    = (const int*)  d_in[2];
    const float* embed = (const float*)d_in[3];
    const float* Wenc  = (const float*)d_in[4];
    const float* benc  = (const float*)d_in[5];
    const float* Wdec  = (const float*)d_in[6];
    const float* Wih0  = (const float*)d_in[7];
    const float* Whh0  = (const float*)d_in[8];
    const float* bih0  = (const float*)d_in[9];
    const float* bhh0  = (const float*)d_in[10];
    const float* Wih1  = (const float*)d_in[11];
    const float* Whh1  = (const float*)d_in[12];
    const float* bih1  = (const float*)d_in[13];
    const float* bhh1  = (const float*)d_in[14];
    const float* Wout  = (const float*)d_in[15];
    const float* bout  = (const float*)d_in[16];
    float* out = (float*)d_out;

    float *pre, *zs, *logits, *z0, *c0, *z1, *c1, *attc, *decP, *g0P, *g1P;
    float *g0Wt, *g1Wt, *decWt;
    cudaGetSymbolAddress((void**)&pre,    g_pre);
    cudaGetSymbolAddress((void**)&zs,     g_zs);
    cudaGetSymbolAddress((void**)&logits, g_logits);
    cudaGetSymbolAddress((void**)&z0,     g_z0);
    cudaGetSymbolAddress((void**)&c0,     g_c0);
    cudaGetSymbolAddress((void**)&z1,     g_z1);
    cudaGetSymbolAddress((void**)&c1,     g_c1);
    cudaGetSymbolAddress((void**)&attc,   g_attc);
    cudaGetSymbolAddress((void**)&decP,   g_decP);
    cudaGetSymbolAddress((void**)&g0P,    g_g0P);
    cudaGetSymbolAddress((void**)&g1P,    g_g1P);
    cudaGetSymbolAddress((void**)&g0Wt,   g_g0Wt);
    cudaGetSymbolAddress((void**)&g1Wt,   g_g1Wt);
    cudaGetSymbolAddress((void**)&decWt,  g_decWt);

    initk<<<2048,256>>>();

    // one-shot weight transposes into k-major layouts
    transpose_k<<<dim3(48,128),256>>>(Wih0, g0Wt, 4*DU, DU+EP, 4*DU, 0);
    transpose_k<<<dim3(32,128),256>>>(Whh0, g0Wt, 4*DU, DU,    4*DU, DU+EP);
    transpose_k<<<dim3(32,128),256>>>(Wih1, g1Wt, 4*DU, DU,    4*DU, 0);
    transpose_k<<<dim3(32,128),256>>>(Whh1, g1Wt, 4*DU, DU,    4*DU, DU);
    transpose_k<<<dim3(32,10),256>>>(Wdec, decWt, AD,   DU,    512,  0);

    // pre_enc = tanh(hs @ Wenc^T + benc):  M=16384, N=320, K=512
    gemm_big<<<dim3(5,128),256>>>(hs, Wenc, benc, pre, BB*TT, AD, EP, 1);

    for (int step = 0; step < LP1; step++){
        // dec partials: z0 @ Wdec^T  (N=320 pad512, 16 k-slices of 64)
        gemm_small3<<<dim3(2,DSPL),128>>>(0, step, decWt, 512, AD,
                                          embed, ys, attc, z0, z1, decP, 64);
        attA_kernel<<<dim3(BB,8),256>>>();
        attC_kernel<<<dim3(BB,4),128>>>(hs, hlens);
        // LSTM0 gates: K=2560, 8 slices of 320
        gemm_small3<<<dim3(16,8),128>>>(1, step, g0Wt, 4*DU, 4*DU,
                                        embed, ys, attc, z0, z1, g0P, 320);
        cellk<<<128,256>>>(g0P, 8, bih0, bhh0, z0, c0, (float*)0, 0);
        // LSTM1 gates: K=2048, 8 slices of 256
        gemm_small3<<<dim3(16,8),128>>>(2, step, g1Wt, 4*DU, 4*DU,
                                        embed, ys, attc, z0, z1, g1P, 256);
        cellk<<<128,256>>>(g1P, 8, bih1, bhh1, z1, c1, zs, step);
    }

    // logits = zs @ Wout^T + bout:  M=4128, N=10000, K=1024
    gemm_big<<<dim3(157,33),256>>>(zs, Wout, bout, logits, NROWS, OD, DU, 0);
    rowstats<<<NROWS,256>>>(ys);
    finalk<<<1,256>>>(out);
    (void)in_sizes; (void)n_in; (void)out_size;
}

// round 16
// speedup vs baseline: 2.2538x; 1.0885x over previous
#include <cuda_runtime.h>
#include <math.h>

typedef unsigned long long ull;

#define BB 32
#define TT 512
#define EP 512
#define DU 1024
#define OD 10000
#define AD 320
#define LL 128
#define LP1 129
#define NROWS (BB*LP1)      /* 4128 */
#define SOS_EOS (OD-1)
#define DSPL 16             /* dec split-K slices */
#define GSPL 16             /* gates split-K slices */

// ---------------- scratch (device globals; no allocation allowed) ----------
__device__ float g_pre[(size_t)BB*TT*AD];       // tanh(hs @ Wenc^T + benc)
__device__ float g_zs[(size_t)BB*LP1*DU];       // z1 history
__device__ float g_logits[(size_t)NROWS*OD];
__device__ float g_z0[BB*DU];
__device__ float g_c0[BB*DU];
__device__ float g_z1[BB*DU];
__device__ float g_c1[BB*DU];
__device__ float g_attc[BB*EP];
__device__ float g_e[BB*TT];
__device__ float g_decP[DSPL*BB*AD];            // dec partials
__device__ float g_g0P[(size_t)GSPL*BB*4*DU];   // gates0 partials
__device__ float g_g1P[(size_t)GSPL*BB*4*DU];   // gates1 partials
__device__ float g_nll[NROWS];
__device__ int   g_corr[NROWS];
// transposed (k-major) weights, built once per call
__device__ float g_g0Wt[(size_t)2560*4096];     // rows: [Wih0 k<1536 | Whh0]
__device__ float g_g1Wt[(size_t)2048*4096];     // rows: [Wih1 k<1024 | Whh1]
__device__ float g_decWt[(size_t)1024*512];     // Wdec^T padded to 512 cols

// ---------------- packed f32x2 helpers -------------------------------------
__device__ __forceinline__ ull pk2(float lo, float hi){
    ull r; asm("mov.b64 %0, {%1, %2};" : "=l"(r) : "f"(lo), "f"(hi)); return r;
}
__device__ __forceinline__ void up2(ull v, float &lo, float &hi){
    asm("mov.b64 {%0, %1}, %2;" : "=f"(lo), "=f"(hi) : "l"(v));
}
__device__ __forceinline__ void fma2(ull &acc, ull a, ull b){
    asm("fma.rn.f32x2 %0, %1, %2, %0;" : "+l"(acc) : "l"(a), "l"(b));
}
// ---------------- cp.async helpers ------------------------------------------
__device__ __forceinline__ void cpa16(void* dst, const void* src){
    unsigned d = (unsigned)__cvta_generic_to_shared(dst);
    asm volatile("cp.async.cg.shared.global [%0], [%1], 16;" :: "r"(d), "l"(src));
}
__device__ __forceinline__ void cpa_commit(){ asm volatile("cp.async.commit_group;"); }
__device__ __forceinline__ void cpa_wait0(){ asm volatile("cp.async.wait_group 0;" ::: "memory"); }

// ---------------- init ------------------------------------------------------
__global__ void initk(){
    int i = blockIdx.x*256 + threadIdx.x;
    if (i < BB*DU){ g_z0[i]=0.f; g_c0[i]=0.f; g_z1[i]=0.f; g_c1[i]=0.f; }
    if (i < 1024*512) g_decWt[i] = 0.f;
}

// ---------------- weight transpose: Wt[kofs+k][n] = W[n][k] -----------------
__global__ __launch_bounds__(256) void transpose_k(
    const float* __restrict__ W, float* __restrict__ Wt,
    int rows, int cols, int ldt, int kofs)
{
    __shared__ float tile[32][33];
    int c0 = blockIdx.x*32, r0 = blockIdx.y*32;
    int x = threadIdx.x & 31, y = threadIdx.x >> 5;
#pragma unroll
    for (int j = 0; j < 4; j++){
        int r = r0 + y + j*8;
        if (r < rows && c0 + x < cols)
            tile[y+j*8][x] = W[(size_t)r*cols + c0 + x];
    }
    __syncthreads();
#pragma unroll
    for (int j = 0; j < 4; j++){
        int k = c0 + y + j*8, n = r0 + x;
        if (k < cols && n < rows)
            Wt[(size_t)(kofs + k)*ldt + n] = tile[x][y+j*8];
    }
}

// ---------------- big GEMM v2: C[M,N] = A[M,K] @ B[N,K]^T + bias, opt tanh --
// 256 threads, BM=128, BN=128, BK=8, tile 8x8, ull2 B-reads, 1 sync/tile.
__global__ __launch_bounds__(256) void gemm_big2(
    const float* __restrict__ A, const float* __restrict__ B,
    const float* __restrict__ bias, float* __restrict__ C,
    int M, int N, int K, int act)
{
    __shared__ __align__(16) float As[2][8][128];
    __shared__ __align__(16) float Bs[2][8][128];
    const int t  = threadIdx.x;
    const int m0 = blockIdx.y * 128;
    const int n0 = blockIdx.x * 128;
    const int mt = (t >> 4) * 8;
    const int nt = (t & 15) * 4;
    const int lr = t >> 1, lq = t & 1;

    ull acc[8][4];
#pragma unroll
    for (int i = 0; i < 8; i++)
#pragma unroll
        for (int j = 0; j < 4; j++) acc[i][j] = 0ULL;

    auto ldA = [&](int k0)->float4 {
        int gm = m0 + lr;
        if (gm < M) return *(const float4*)(A + (size_t)gm*K + k0 + lq*4);
        return make_float4(0.f,0.f,0.f,0.f);
    };
    auto ldB = [&](int k0)->float4 {
        int gn = n0 + lr;
        if (gn < N) return *(const float4*)(B + (size_t)gn*K + k0 + lq*4);
        return make_float4(0.f,0.f,0.f,0.f);
    };

    {
        float4 va = ldA(0), vb = ldB(0);
        As[0][lq*4+0][lr]=va.x; As[0][lq*4+1][lr]=va.y;
        As[0][lq*4+2][lr]=va.z; As[0][lq*4+3][lr]=va.w;
        Bs[0][lq*4+0][lr]=vb.x; Bs[0][lq*4+1][lr]=vb.y;
        Bs[0][lq*4+2][lr]=vb.z; Bs[0][lq*4+3][lr]=vb.w;
    }
    __syncthreads();

    const int NK = K >> 3;
    for (int it = 0; it < NK; it++){
        const int buf = it & 1, nb = buf ^ 1;
        const bool pf = (it + 1 < NK);
        float4 va, vb;
        if (pf){ va = ldA((it+1)*8); vb = ldB((it+1)*8); }
#pragma unroll
        for (int kk = 0; kk < 8; kk++){
            float4 a0 = *(const float4*)&As[buf][kk][mt];
            float4 a1 = *(const float4*)&As[buf][kk][mt+4];
            ulonglong2 b0 = *(const ulonglong2*)&Bs[buf][kk][nt];
            ulonglong2 b1 = *(const ulonglong2*)&Bs[buf][kk][nt+64];
            float av[8] = {a0.x,a0.y,a0.z,a0.w,a1.x,a1.y,a1.z,a1.w};
#pragma unroll
            for (int i = 0; i < 8; i++){
                ull ad = pk2(av[i], av[i]);
                fma2(acc[i][0], ad, b0.x);
                fma2(acc[i][1], ad, b0.y);
                fma2(acc[i][2], ad, b1.x);
                fma2(acc[i][3], ad, b1.y);
            }
        }
        if (pf){
            As[nb][lq*4+0][lr]=va.x; As[nb][lq*4+1][lr]=va.y;
            As[nb][lq*4+2][lr]=va.z; As[nb][lq*4+3][lr]=va.w;
            Bs[nb][lq*4+0][lr]=vb.x; Bs[nb][lq*4+1][lr]=vb.y;
            Bs[nb][lq*4+2][lr]=vb.z; Bs[nb][lq*4+3][lr]=vb.w;
        }
        __syncthreads();
    }

    float bs0[4], bs1[4];
#pragma unroll
    for (int j = 0; j < 4; j++){
        bs0[j] = (n0+nt+j    < N) ? bias[n0+nt+j]    : 0.f;
        bs1[j] = (n0+64+nt+j < N) ? bias[n0+64+nt+j] : 0.f;
    }
#pragma unroll
    for (int i = 0; i < 8; i++){
        int gm = m0 + mt + i;
        if (gm >= M) continue;
        float v[8];
        up2(acc[i][0], v[0], v[1]); up2(acc[i][1], v[2], v[3]);
        up2(acc[i][2], v[4], v[5]); up2(acc[i][3], v[6], v[7]);
#pragma unroll
        for (int j = 0; j < 4; j++){
            v[j]   += bs0[j];
            v[4+j] += bs1[j];
        }
        if (act){
#pragma unroll
            for (int j = 0; j < 8; j++) v[j] = tanhf(v[j]);
        }
        int c = n0 + nt;
        if (c + 3 < N) *(float4*)(C + (size_t)gm*N + c) = make_float4(v[0],v[1],v[2],v[3]);
        else { for (int j = 0; j < 4; j++) if (c+j < N) C[(size_t)gm*N + c + j] = v[j]; }
        c = n0 + 64 + nt;
        if (c + 3 < N) *(float4*)(C + (size_t)gm*N + c) = make_float4(v[4],v[5],v[6],v[7]);
        else { for (int j = 0; j < 4; j++) if (c+j < N) C[(size_t)gm*N + c + j] = v[4+j]; }
    }
}

// ---------------- recurrent small-M GEMM v4 ---------------------------------
// P[s][32][N] = A[32, kslice] @ Wt[kslice, N]  (Wt k-major, row stride ldw)
// 256 threads, tile 8b x 8n, 512 cols/block, BK=8, cp.async B, 1 sync/tile.
// A gathered per mode: 0: z0 ; 1: [embed | att_c | z0] ; 2: [z0 | z1]
__global__ __launch_bounds__(256) void gemm_small3(
    int mode, int step, const float* __restrict__ Wt, int ldw, int N,
    const float* __restrict__ embed, const int* __restrict__ ys,
    const float* __restrict__ attc, const float* __restrict__ x0,
    const float* __restrict__ x1, float* __restrict__ P, int kPerSplit)
{
    __shared__ __align__(16) float As[2][8][32];
    __shared__ __align__(16) float Bs[2][8][512];
    const int t    = threadIdx.x;
    const int bt   = (t >> 6) * 8;
    const int nt   = (t & 63) * 4;
    const int n0   = blockIdx.x * 512;
    const int s    = blockIdx.y;
    const int kbeg = s * kPerSplit;
    const int NK   = kPerSplit >> 3;
    const int ab   = t >> 1;      // t<64: batch row for A load
    const int akq  = t & 1;       // k-quad (0/1)

    ull acc[8][4];
#pragma unroll
    for (int i = 0; i < 8; i++)
#pragma unroll
        for (int j = 0; j < 4; j++) acc[i][j] = 0ULL;

    auto loadA = [&](int it)->float4 {
        int kg = kbeg + it*8 + akq*4;
        const float* src;
        if (mode == 1){
            if (kg < DU){
                int tok = (step == 0) ? SOS_EOS : ys[ab*LL + step - 1];
                src = embed + (size_t)tok*DU + kg;
            } else if (kg < DU + EP){
                src = attc + ab*EP + (kg - DU);
            } else {
                src = x0 + ab*DU + (kg - DU - EP);
            }
        } else if (mode == 2){
            src = (kg < DU) ? (x0 + ab*DU + kg) : (x1 + ab*DU + (kg - DU));
        } else {
            src = x0 + ab*DU + kg;
        }
        return *(const float4*)src;
    };
    auto loadB = [&](int it, int bufi){
        int krow = kbeg + it*8;
#pragma unroll
        for (int l = 0; l < 4; l++){
            int idx = l*256 + t;
            int row = idx >> 7, c4 = (idx & 127) * 4;
            cpa16(&Bs[bufi][row][c4], Wt + (size_t)(krow+row)*ldw + n0 + c4);
        }
        cpa_commit();
    };

    // prologue
    {
        loadB(0, 0);
        float4 ra;
        if (t < 64) ra = loadA(0);
        cpa_wait0();
        if (t < 64){
            As[0][akq*4+0][ab]=ra.x; As[0][akq*4+1][ab]=ra.y;
            As[0][akq*4+2][ab]=ra.z; As[0][akq*4+3][ab]=ra.w;
        }
        __syncthreads();
    }

    for (int it = 0; it < NK; it++){
        const int buf = it & 1, nb = buf ^ 1;
        const bool pf = (it + 1 < NK);
        float4 rn;
        if (pf){
            loadB(it+1, nb);
            if (t < 64) rn = loadA(it+1);
        }
#pragma unroll
        for (int kk = 0; kk < 8; kk++){
            float4 a0 = *(const float4*)&As[buf][kk][bt];
            float4 a1 = *(const float4*)&As[buf][kk][bt+4];
            ulonglong2 b0 = *(const ulonglong2*)&Bs[buf][kk][nt];
            ulonglong2 b1 = *(const ulonglong2*)&Bs[buf][kk][nt+256];
            float av[8] = {a0.x,a0.y,a0.z,a0.w,a1.x,a1.y,a1.z,a1.w};
#pragma unroll
            for (int i = 0; i < 8; i++){
                ull ad = pk2(av[i], av[i]);
                fma2(acc[i][0], ad, b0.x);
                fma2(acc[i][1], ad, b0.y);
                fma2(acc[i][2], ad, b1.x);
                fma2(acc[i][3], ad, b1.y);
            }
        }
        if (pf){
            cpa_wait0();
            if (t < 64){
                As[nb][akq*4+0][ab]=rn.x; As[nb][akq*4+1][ab]=rn.y;
                As[nb][akq*4+2][ab]=rn.z; As[nb][akq*4+3][ab]=rn.w;
            }
        }
        __syncthreads();
    }

    // epilogue
#pragma unroll
    for (int i = 0; i < 8; i++){
        int b = bt + i;
        float v[8];
        up2(acc[i][0], v[0], v[1]); up2(acc[i][1], v[2], v[3]);
        up2(acc[i][2], v[4], v[5]); up2(acc[i][3], v[6], v[7]);
        size_t base = ((size_t)s*BB + b)*(size_t)N;
        int c = n0 + nt;
        if (c + 3 < N) *(float4*)&P[base + c] = make_float4(v[0],v[1],v[2],v[3]);
        else { for (int j = 0; j < 4; j++) if (c+j < N) P[base + c + j] = v[j]; }
        c = n0 + 256 + nt;
        if (c + 3 < N) *(float4*)&P[base + c] = make_float4(v[4],v[5],v[6],v[7]);
        else { for (int j = 0; j < 4; j++) if (c+j < N) P[base + c + j] = v[4+j]; }
    }
}

// ---------------- attention phase A: dec reduce+tanh, e = pre . dec ---------
// grid (B, 16): block (b, ts) computes e[b, ts*32 .. ts*32+32)
__global__ __launch_bounds__(256) void attA_kernel()
{
    const int b  = blockIdx.x;
    const int ts = blockIdx.y;
    const int t  = threadIdx.x;
    __shared__ float dec_s[AD];

    for (int a = t; a < AD; a += 256){
        float sv = 0.f;
#pragma unroll
        for (int s = 0; s < DSPL; s++) sv += g_decP[((size_t)s*BB + b)*AD + a];
        dec_s[a] = tanhf(sv);
    }
    __syncthreads();

    const int warp = t >> 5, lane = t & 31;
    const float* pr = &g_pre[((size_t)b*TT + (size_t)ts*32)*AD];
#pragma unroll
    for (int rr = warp; rr < 32; rr += 8){
        const float* p = pr + (size_t)rr*AD;
        float sv = 0.f;
#pragma unroll
        for (int a = lane; a < AD; a += 32) sv += p[a]*dec_s[a];
#pragma unroll
        for (int o = 16; o; o >>= 1) sv += __shfl_xor_sync(0xffffffffu, sv, o);
        if (lane == 0) g_e[b*TT + ts*32 + rr] = sv;
    }
}

// ---------------- attention phase C: softmax + att_c d-slice ----------------
// grid (B, 4), 256 threads: block (b, dt) computes att_c[b, dt*128 .. +128)
__global__ __launch_bounds__(256) void attC_kernel(
    const float* __restrict__ hs, const int* __restrict__ hlens)
{
    const int b  = blockIdx.x;
    const int dt = blockIdx.y;
    const int t  = threadIdx.x;
    __shared__ float red[256];
    __shared__ float w_s[TT];
    __shared__ float part[256];

    const int hlen = hlens[b];
    const float* eb = &g_e[b*TT];
    float v0 = (t       < hlen) ? 2.f*eb[t]       : -1e10f;
    float v1 = (t + 256 < hlen) ? 2.f*eb[t + 256] : -1e10f;
    red[t] = fmaxf(v0, v1); __syncthreads();
    for (int o = 128; o; o >>= 1){ if (t < o) red[t] = fmaxf(red[t], red[t+o]); __syncthreads(); }
    float mx = red[0]; __syncthreads();
    float e0 = expf(v0 - mx), e1 = expf(v1 - mx);
    red[t] = e0 + e1; __syncthreads();
    for (int o = 128; o; o >>= 1){ if (t < o) red[t] += red[t+o]; __syncthreads(); }
    float inv = 1.f / red[0];
    __syncthreads();
    w_s[t] = e0*inv; w_s[t+256] = e1*inv;
    __syncthreads();

    // att_c[b, d] over t-halves; d = dt*128 + (t&127), half = t>>7
    const int d = dt*128 + (t & 127);
    const int tt0 = (t >> 7) * 256;
    const float* hb = hs + (size_t)b*TT*EP + d;
    float a0=0.f, a1=0.f, a2=0.f, a3=0.f;
#pragma unroll 4
    for (int tt = tt0; tt < tt0 + 256; tt += 4){
        a0 += w_s[tt+0]*hb[(size_t)(tt+0)*EP];
        a1 += w_s[tt+1]*hb[(size_t)(tt+1)*EP];
        a2 += w_s[tt+2]*hb[(size_t)(tt+2)*EP];
        a3 += w_s[tt+3]*hb[(size_t)(tt+3)*EP];
    }
    part[t] = (a0+a1) + (a2+a3);
    __syncthreads();
    if (t < 128) g_attc[b*EP + dt*128 + t] = part[t] + part[t + 128];
}

// ---------------- LSTM cell: reduce split-K partials + biases, gate math ----
__global__ void cellk(const float* __restrict__ P, int S,
                      const float* __restrict__ bi, const float* __restrict__ bh,
                      float* __restrict__ h, float* __restrict__ c,
                      float* __restrict__ zsOut, int step)
{
    int idx = blockIdx.x*256 + threadIdx.x;
    if (idx >= BB*DU) return;
    int b = idx / DU, u = idx % DU;
    float gi=0.f, gf=0.f, gg=0.f, go=0.f;
    const float* p = P + (size_t)b*4*DU + u;
    for (int s = 0; s < S; s++){
        gi += p[0]; gf += p[DU]; gg += p[2*DU]; go += p[3*DU];
        p += (size_t)BB*4*DU;
    }
    gi += bi[u]        + bh[u];
    gf += bi[DU+u]     + bh[DU+u];
    gg += bi[2*DU+u]   + bh[2*DU+u];
    go += bi[3*DU+u]   + bh[3*DU+u];
    float I = 1.f/(1.f+expf(-gi));
    float F = 1.f/(1.f+expf(-gf));
    float G = tanhf(gg);
    float O = 1.f/(1.f+expf(-go));
    float cn = F*c[idx] + I*G;
    c[idx] = cn;
    float hn = O*tanhf(cn);
    h[idx] = hn;
    if (zsOut) zsOut[((size_t)b*LP1 + step)*DU + u] = hn;
}

// ---------------- per-row log-softmax stats on logits -----------------------
__global__ void rowstats(const int* __restrict__ ys)
{
    const int r = blockIdx.x;
    const int b = r / LP1, l = r % LP1;
    const float* row = &g_logits[(size_t)r*OD];
    const int t = threadIdx.x;
    __shared__ float sm[256];
    __shared__ int   si[256];

    float mx = -1e30f; int mi = OD;
    for (int o = t; o < OD; o += 256){
        float v = row[o];
        if (v > mx){ mx = v; mi = o; }
    }
    sm[t] = mx; si[t] = mi; __syncthreads();
    for (int o = 128; o; o >>= 1){
        if (t < o){
            if (sm[t+o] > sm[t] || (sm[t+o] == sm[t] && si[t+o] < si[t])){
                sm[t] = sm[t+o]; si[t] = si[t+o];
            }
        }
        __syncthreads();
    }
    float M = sm[0]; int amax = si[0];
    __syncthreads();

    float s = 0.f;
    for (int o = t; o < OD; o += 256) s += expf(row[o] - M);
    sm[t] = s; __syncthreads();
    for (int o = 128; o; o >>= 1){ if (t < o) sm[t] += sm[t+o]; __syncthreads(); }
    if (t == 0){
        int tgt = (l < LL) ? ys[b*LL + l] : SOS_EOS;
        float lse = M + logf(sm[0]);
        g_nll[r]  = lse - row[tgt];
        g_corr[r] = (amax == tgt) ? 1 : 0;
    }
}

// ---------------- final reduction: loss, acc, ppl ---------------------------
__global__ void finalk(float* __restrict__ out)
{
    __shared__ double sd[256];
    __shared__ int    sc[256];
    const int t = threadIdx.x;
    double s = 0.0; int c = 0;
    for (int r = t; r < NROWS; r += 256){ s += (double)g_nll[r]; c += g_corr[r]; }
    sd[t] = s; sc[t] = c; __syncthreads();
    for (int o = 128; o; o >>= 1){ if (t < o){ sd[t]+=sd[t+o]; sc[t]+=sc[t+o]; } __syncthreads(); }
    if (t == 0){
        double loss = sd[0] / (double)NROWS * (double)LL;
        out[0] = (float)loss;
        out[1] = (float)((double)sc[0] / (double)NROWS);
        out[2] = (float)exp(loss / (double)BB);
    }
}

// ---------------- host orchestration ----------------------------------------
extern "C" void kernel_launch(void* const* d_in, const int* in_sizes, int n_in,
                              void* d_out, int out_size)
{
    const float* hs    = (const float*)d_in[0];
    const int*   hlens = (const int*)  d_in[1];
    const int*   ys    = (const int*)  d_in[2];
    const float* embed = (const float*)d_in[3];
    const float* Wenc  = (const float*)d_in[4];
    const float* benc  = (const float*)d_in[5];
    const float* Wdec  = (const float*)d_in[6];
    const float* Wih0  = (const float*)d_in[7];
    const float* Whh0  = (const float*)d_in[8];
    const float* bih0  = (const float*)d_in[9];
    const float* bhh0  = (const float*)d_in[10];
    const float* Wih1  = (const float*)d_in[11];
    const float* Whh1  = (const float*)d_in[12];
    const float* bih1  = (const float*)d_in[13];
    const float* bhh1  = (const float*)d_in[14];
    const float* Wout  = (const float*)d_in[15];
    const float* bout  = (const float*)d_in[16];
    float* out = (float*)d_out;

    float *pre, *zs, *logits, *z0, *c0, *z1, *c1, *attc, *decP, *g0P, *g1P;
    float *g0Wt, *g1Wt, *decWt;
    cudaGetSymbolAddress((void**)&pre,    g_pre);
    cudaGetSymbolAddress((void**)&zs,     g_zs);
    cudaGetSymbolAddress((void**)&logits, g_logits);
    cudaGetSymbolAddress((void**)&z0,     g_z0);
    cudaGetSymbolAddress((void**)&c0,     g_c0);
    cudaGetSymbolAddress((void**)&z1,     g_z1);
    cudaGetSymbolAddress((void**)&c1,     g_c1);
    cudaGetSymbolAddress((void**)&attc,   g_attc);
    cudaGetSymbolAddress((void**)&decP,   g_decP);
    cudaGetSymbolAddress((void**)&g0P,    g_g0P);
    cudaGetSymbolAddress((void**)&g1P,    g_g1P);
    cudaGetSymbolAddress((void**)&g0Wt,   g_g0Wt);
    cudaGetSymbolAddress((void**)&g1Wt,   g_g1Wt);
    cudaGetSymbolAddress((void**)&decWt,  g_decWt);

    initk<<<2048,256>>>();

    // one-shot weight transposes into k-major layouts
    transpose_k<<<dim3(48,128),256>>>(Wih0, g0Wt, 4*DU, DU+EP, 4*DU, 0);
    transpose_k<<<dim3(32,128),256>>>(Whh0, g0Wt, 4*DU, DU,    4*DU, DU+EP);
    transpose_k<<<dim3(32,128),256>>>(Wih1, g1Wt, 4*DU, DU,    4*DU, 0);
    transpose_k<<<dim3(32,128),256>>>(Whh1, g1Wt, 4*DU, DU,    4*DU, DU);
    transpose_k<<<dim3(32,10),256>>>(Wdec, decWt, AD,   DU,    512,  0);

    // pre_enc = tanh(hs @ Wenc^T + benc):  M=16384, N=320, K=512
    gemm_big2<<<dim3(3,128),256>>>(hs, Wenc, benc, pre, BB*TT, AD, EP, 1);

    for (int step = 0; step < LP1; step++){
        // dec partials: z0 @ Wdec^T  (N=320 pad512, 16 k-slices of 64)
        gemm_small3<<<dim3(1,DSPL),256>>>(0, step, decWt, 512, AD,
                                          embed, ys, attc, z0, z1, decP, 64);
        attA_kernel<<<dim3(BB,16),256>>>();
        attC_kernel<<<dim3(BB,4),256>>>(hs, hlens);
        // LSTM0 gates: K=2560, 16 slices of 160
        gemm_small3<<<dim3(8,GSPL),256>>>(1, step, g0Wt, 4*DU, 4*DU,
                                          embed, ys, attc, z0, z1, g0P, 160);
        cellk<<<128,256>>>(g0P, GSPL, bih0, bhh0, z0, c0, (float*)0, 0);
        // LSTM1 gates: K=2048, 16 slices of 128
        gemm_small3<<<dim3(8,GSPL),256>>>(2, step, g1Wt, 4*DU, 4*DU,
                                          embed, ys, attc, z0, z1, g1P, 128);
        cellk<<<128,256>>>(g1P, GSPL, bih1, bhh1, z1, c1, zs, step);
    }

    // logits = zs @ Wout^T + bout:  M=4128, N=10000, K=1024
    gemm_big2<<<dim3(79,33),256>>>(zs, Wout, bout, logits, NROWS, OD, DU, 0);
    rowstats<<<NROWS,256>>>(ys);
    finalk<<<1,256>>>(out);
    (void)in_sizes; (void)n_in; (void)out_size;
}